// round 13
// baseline (speedup 1.0000x reference)
#include <cuda_runtime.h>
#include <math.h>

#define NMAX 100000
#define EMAX 1600000
#define H 32
#define BN_EPS 1e-5f
#define NBANK 32
#define NBMAX ((NMAX + 255) / 256)

// ---------------- device scratch ----------------
__device__ int      g_csr[EMAX];
__device__ int      g_rowstart[NMAX];
__device__ int      g_cursor[NMAX];
__device__ int      g_deg[NMAX];
__device__ float    g_dinv[NMAX];
__device__ float    g_sdinv[NMAX];              // sum of dinv over nbrs + self
__device__ __align__(16) float4 g_x4[NMAX];     // (x*dinv, dinv)
__device__ __align__(16) float g_sA[NMAX * H];  // h'·dinv ping
__device__ __align__(16) float g_sB[NMAX * H];  // h'·dinv pong
__device__ __align__(16) float g_h[NMAX * H];   // final-layer features
__device__ float    g_r[NMAX];
__device__ double   g_sumb[NBANK][H], g_sumsqb[NBANK][H];  // banked BN stats
__device__ float    g_Wp[H * H];
__device__ float    g_kvec[H];
__device__ unsigned g_rmax_bits;
__device__ double   g_sumexp;
__device__ double   g_wsum[H];
__device__ int      g_blockcnt[NBMAX], g_blockoff[NBMAX], g_C;

__device__ __forceinline__ float warp_sum(float v) {
#pragma unroll
    for (int o = 16; o > 0; o >>= 1) v += __shfl_xor_sync(0xffffffffu, v, o);
    return v;
}

// warp-per-node gather over one feature table: coalesced index load + shuffle
__device__ __forceinline__ float csr_gather_row(const float* __restrict__ tab,
                                                int start, int deg, int c) {
    float r = 0.f;
    for (int k = 0; k < deg; k += 32) {
        int rem = deg - k;
        int myi = (c < rem) ? g_csr[start + k + c] : 0;
        int cnt = (rem < 32) ? rem : 32;
#pragma unroll
        for (int j = 0; j < 32; j++) {
            if (j < cnt) {
                int sj = __shfl_sync(0xffffffffu, myi, j);
                r += tab[(size_t)sj * H + c];
            }
        }
    }
    return r;
}

// ---------------- kernels ----------------
__global__ void k_init(int n) {
    int i = blockIdx.x * blockDim.x + threadIdx.x;
    if (i < n) { g_deg[i] = 0; g_cursor[i] = 0; }
    if (i < NBANK * H) { g_sumb[i >> 5][i & 31] = 0.0; g_sumsqb[i >> 5][i & 31] = 0.0; }
    if (i < H) g_wsum[i] = 0.0;
    if (i == 0) { g_rmax_bits = 0u; g_sumexp = 0.0; }
}

__global__ void k_prep_edges(const int* __restrict__ ei, int e, int n) {
    int t = blockIdx.x * blockDim.x + threadIdx.x;
    if (t >= e) return;
    int d = ei[e + t];
    if ((unsigned)d >= (unsigned)n) d = 0;
    atomicAdd(&g_deg[d], 1);
}

__global__ void k_dinv_x4(const float* __restrict__ x, int n) {
    int i = blockIdx.x * blockDim.x + threadIdx.x;
    if (i >= n) return;
    float di = rsqrtf((float)(g_deg[i] + 1));
    g_dinv[i] = di;
    g_x4[i] = make_float4(x[(size_t)i * 3 + 0] * di,
                          x[(size_t)i * 3 + 1] * di,
                          x[(size_t)i * 3 + 2] * di, di);
}

__global__ void k_degsum_block(int n) {
    __shared__ int sh[256];
    int tid = threadIdx.x;
    int i = blockIdx.x * 256 + tid;
    int v = (i < n) ? g_deg[i] : 0;
    sh[tid] = v;
    __syncthreads();
#pragma unroll
    for (int off = 1; off < 256; off <<= 1) {
        int t = (tid >= off) ? sh[tid - off] : 0;
        __syncthreads();
        sh[tid] += t;
        __syncthreads();
    }
    if (tid == 255) g_blockcnt[blockIdx.x] = sh[255];
}

__global__ void k_scan_par(int nb, int setC) {
    __shared__ int sh[512];
    int tid = threadIdx.x;
    int v = (tid < nb) ? g_blockcnt[tid] : 0;
    sh[tid] = v;
    __syncthreads();
#pragma unroll
    for (int off = 1; off < 512; off <<= 1) {
        int t = (tid >= off) ? sh[tid - off] : 0;
        __syncthreads();
        sh[tid] += t;
        __syncthreads();
    }
    if (tid < nb) g_blockoff[tid] = sh[tid] - v;
    if (setC && tid == nb - 1) g_C = sh[tid];
}

__global__ void k_rowstart(int n) {
    __shared__ int sh[256];
    int tid = threadIdx.x;
    int i = blockIdx.x * 256 + tid;
    int v = (i < n) ? g_deg[i] : 0;
    sh[tid] = v;
    __syncthreads();
#pragma unroll
    for (int off = 1; off < 256; off <<= 1) {
        int t = (tid >= off) ? sh[tid - off] : 0;
        __syncthreads();
        sh[tid] += t;
        __syncthreads();
    }
    if (i < n) g_rowstart[i] = g_blockoff[blockIdx.x] + sh[tid] - v;
}

__global__ void k_bucket(const int* __restrict__ ei, int e, int n) {
    int t = blockIdx.x * blockDim.x + threadIdx.x;
    if (t >= e) return;
    int s = ei[t];
    int d = ei[e + t];
    if ((unsigned)s >= (unsigned)n) s = 0;
    if ((unsigned)d >= (unsigned)n) d = 0;
    int pos = g_rowstart[d] + atomicAdd(&g_cursor[d], 1);
    g_csr[pos] = s;
}

// conv1: rank-3 gather + W1 + bias/relu + banked stats; stores h1·dinv and sdinv
__global__ void k_conv1(const float* __restrict__ W, const float* __restrict__ bias,
                        int n) {
    __shared__ float Wsh[3 * H];
    __shared__ float sv[8][H], sq[8][H];
    int tid = threadIdx.x;
    for (int t = tid; t < 3 * H; t += 256) Wsh[t] = W[t];
    __syncthreads();
    int c = tid & 31, w = tid >> 5;
    int i = blockIdx.x * 8 + w;
    float v = 0.f;
    if (i < n) {
        int start = g_rowstart[i];
        int deg = g_deg[i];
        float ax = 0.f, ay = 0.f, az = 0.f, aw = 0.f;
        for (int k = c; k < deg; k += 32) {
            float4 t4 = g_x4[g_csr[start + k]];
            ax += t4.x; ay += t4.y; az += t4.z; aw += t4.w;
        }
        ax = warp_sum(ax); ay = warp_sum(ay); az = warp_sum(az); aw = warp_sum(aw);
        float4 self = g_x4[i];
        ax += self.x; ay += self.y; az += self.z; aw += self.w;
        if (c == 0) g_sdinv[i] = aw;
        float di = g_dinv[i];
        float z = ax * Wsh[0 * H + c] + ay * Wsh[1 * H + c] + az * Wsh[2 * H + c];
        v = fmaxf(z * di + bias[c], 0.f);
        g_sA[(size_t)i * H + c] = v * di;
    }
    sv[w][c] = v; sq[w][c] = v * v;
    __syncthreads();
    if (tid < H) {
        float s = 0.f, q = 0.f;
#pragma unroll
        for (int ww = 0; ww < 8; ww++) { s += sv[ww][tid]; q += sq[ww][tid]; }
        int b = blockIdx.x & (NBANK - 1);
        atomicAdd(&g_sumb[b][tid], (double)s);
        atomicAdd(&g_sumsqb[b][tid], (double)q);
    }
}

// BN params folded into next layer's weight (reads banked stats, zeroes them)
__global__ void k_bnparams(const float* __restrict__ W, const float* __restrict__ g,
                           const float* __restrict__ be, double inv_n) {
    __shared__ float sscale[H], sshift[H];
    int k = threadIdx.x, j = threadIdx.y;
    if (j == 0) {
        double s = 0.0, q = 0.0;
        for (int b = 0; b < NBANK; b++) { s += g_sumb[b][k]; q += g_sumsqb[b][k]; }
        double mu = s * inv_n;
        double var = q * inv_n - mu * mu;
        float scale = g[k] * rsqrtf((float)var + BN_EPS);
        sscale[k] = scale;
        sshift[k] = be[k] - (float)mu * scale;
    }
    __syncthreads();
    float wv = W[k * H + j];
    g_Wp[k * H + j] = sscale[k] * wv;
    float t = sshift[k] * wv;
#pragma unroll
    for (int o = 16; o > 0; o >>= 1) t += __shfl_xor_sync(0xffffffffu, t, o);
    if (k == 0) g_kvec[j] = t;
    g_sumb[j][k] = 0.0;
    g_sumsqb[j][k] = 0.0;
}

// conv2: shuffle-gather + matmul after reduce + bias/relu + banked stats
__global__ void k_conv2(const float* __restrict__ bias, int n) {
    __shared__ float Wsh[H * H];
    __shared__ float kv[H];
    __shared__ float sv[8][H], sq[8][H];
    int tid = threadIdx.x;
    for (int t = tid; t < H * H; t += 256) Wsh[t] = g_Wp[t];
    if (tid < H) kv[tid] = g_kvec[tid];
    __syncthreads();
    int c = tid & 31, w = tid >> 5;
    int i = blockIdx.x * 8 + w;
    float v = 0.f;
    if (i < n) {
        int start = g_rowstart[i];
        int deg = g_deg[i];
        float r = g_sA[(size_t)i * H + c] + csr_gather_row(g_sA, start, deg, c);
        float z = kv[c] * g_sdinv[i];
#pragma unroll
        for (int kk = 0; kk < H; kk++)
            z += __shfl_sync(0xffffffffu, r, kk) * Wsh[kk * H + c];
        float di = g_dinv[i];
        v = fmaxf(z * di + bias[c], 0.f);
        g_sB[(size_t)i * H + c] = v * di;
    }
    sv[w][c] = v; sq[w][c] = v * v;
    __syncthreads();
    if (tid < H) {
        float s = 0.f, q = 0.f;
#pragma unroll
        for (int ww = 0; ww < 8; ww++) { s += sv[ww][tid]; q += sq[ww][tid]; }
        int b = blockIdx.x & (NBANK - 1);
        atomicAdd(&g_sumb[b][tid], (double)s);
        atomicAdd(&g_sumsqb[b][tid], (double)q);
    }
}

// conv3: shuffle-gather + matmul + bias/relu; store h; rowsum + block-level max
__global__ void k_conv3(const float* __restrict__ bias, int n) {
    __shared__ float Wsh[H * H];
    __shared__ float kv[H];
    __shared__ unsigned bmax;
    int tid = threadIdx.x;
    for (int t = tid; t < H * H; t += 256) Wsh[t] = g_Wp[t];
    if (tid < H) kv[tid] = g_kvec[tid];
    if (tid == 0) bmax = 0u;
    __syncthreads();
    int c = tid & 31, w = tid >> 5;
    int i = blockIdx.x * 8 + w;
    if (i < n) {
        int start = g_rowstart[i];
        int deg = g_deg[i];
        float r = g_sB[(size_t)i * H + c] + csr_gather_row(g_sB, start, deg, c);
        float z = kv[c] * g_sdinv[i];
#pragma unroll
        for (int kk = 0; kk < H; kk++)
            z += __shfl_sync(0xffffffffu, r, kk) * Wsh[kk * H + c];
        float v = fmaxf(z * g_dinv[i] + bias[c], 0.f);
        g_h[(size_t)i * H + c] = v;
        float rs = warp_sum(v);
        if (c == 0) {
            g_r[i] = rs;
            atomicMax(&bmax, __float_as_uint(rs));   // rs >= 0
        }
    }
    __syncthreads();
    if (tid == 0) atomicMax(&g_rmax_bits, bmax);
}

__global__ void k_softmax_acc(int n) {
    __shared__ double sw[H];
    __shared__ double se;
    int tid = threadIdx.x;
    if (tid < H) sw[tid] = 0.0;
    if (tid == 0) se = 0.0;
    __syncthreads();
    int lane = tid & 31;
    int gw = blockIdx.x * 8 + (tid >> 5);
    int nw = gridDim.x * 8;
    float rmax = __uint_as_float(g_rmax_bits);
    double acc = 0.0, eacc = 0.0;
    for (int i = gw; i < n; i += nw) {
        float ev = expf(g_r[i] - rmax);
        acc += (double)(ev * g_h[(size_t)i * H + lane]);
        if (lane == 0) eacc += (double)ev;
    }
    atomicAdd(&sw[lane], acc);
    if (lane == 0) atomicAdd(&se, eacc);
    __syncthreads();
    if (tid < H) atomicAdd(&g_wsum[tid], sw[tid]);
    if (tid == 0) atomicAdd(&g_sumexp, se);
}

__global__ void k_count(const int* __restrict__ nt, int n) {
    int i = blockIdx.x * 256 + threadIdx.x;
    int flag = (i < n && nt[i] == 0);
    int cnt = __syncthreads_count(flag);
    if (threadIdx.x == 0) g_blockcnt[blockIdx.x] = cnt;
}

__global__ void __launch_bounds__(256)
k_cand(const int* __restrict__ nt,
       const float* __restrict__ Wc1, const float* __restrict__ bc1,
       const float* __restrict__ Wc2, const float* __restrict__ bc2,
       float* __restrict__ out, int n, int out_size) {
    __shared__ float W1s[H * 16], b1s[16], W2s[16];
    __shared__ float b2s;
    __shared__ int warpsum[8], warpoff[8];
    int tid = threadIdx.x;
    for (int t = tid; t < H * 16; t += 256) W1s[t] = Wc1[t];
    if (tid < 16) { b1s[tid] = bc1[tid]; W2s[tid] = Wc2[tid]; }
    if (tid == 0) b2s = bc2[0];
    int i = blockIdx.x * 256 + tid;
    int flag = (i < n && nt[i] == 0);
    unsigned mask = __ballot_sync(0xffffffffu, flag);
    int lane = tid & 31, w = tid >> 5;
    if (lane == 0) warpsum[w] = __popc(mask);
    __syncthreads();
    if (tid == 0) {
        int run = 0;
#pragma unroll
        for (int ww = 0; ww < 8; ww++) { warpoff[ww] = run; run += warpsum[ww]; }
    }
    __syncthreads();
    if (!flag) return;
    int pos = g_blockoff[blockIdx.x] + warpoff[w] + __popc(mask & ((1u << lane) - 1));
    const float* hr = g_h + (size_t)i * H;
    float hreg[H];
#pragma unroll
    for (int k = 0; k < H; k++) hreg[k] = hr[k];
    float score = b2s;
#pragma unroll
    for (int j = 0; j < 16; j++) {
        float z = b1s[j];
#pragma unroll
        for (int k = 0; k < H; k++) z += hreg[k] * W1s[k * 16 + j];
        score += fmaxf(z, 0.f) * W2s[j];
    }
    int C = g_C;
    if (pos < out_size) out[pos] = score;
    int ip = C + 1 + pos;
    if (ip < out_size) out[ip] = (float)i;
}

__global__ void k_dn(const float* __restrict__ Wd1, const float* __restrict__ bd1,
                     const float* __restrict__ Wd2, const float* __restrict__ bd2,
                     float* __restrict__ out, int out_size) {
    int lane = threadIdx.x;
    double se = g_sumexp;
    float gv = (float)(g_wsum[lane] / se);
    float acc = (lane < 16) ? bd1[lane] : 0.f;
#pragma unroll
    for (int k = 0; k < H; k++) {
        float gk = __shfl_sync(0xffffffffu, gv, k);
        acc += gk * ((lane < 16) ? Wd1[k * 16 + lane] : 0.f);
    }
    float z = fmaxf(acc, 0.f);
    float t = (lane < 16) ? z * Wd2[lane] : 0.f;
    t = warp_sum(t);
    if (lane == 0) {
        int C = g_C;
        if (C < out_size) out[C] = t + bd2[0];
    }
}

// ---------------- host ----------------
extern "C" void kernel_launch(void* const* d_in, const int* in_sizes, int n_in,
                              void* d_out, int out_size) {
    const float* x   = (const float*)d_in[0];
    const int*   ei  = (const int*)d_in[1];
    const int*   nt  = (const int*)d_in[2];
    const float* W1  = (const float*)d_in[3];
    const float* b1  = (const float*)d_in[4];
    const float* W2  = (const float*)d_in[5];
    const float* b2  = (const float*)d_in[6];
    const float* W3  = (const float*)d_in[7];
    const float* b3  = (const float*)d_in[8];
    const float* g1  = (const float*)d_in[9];
    const float* be1 = (const float*)d_in[10];
    const float* g2  = (const float*)d_in[11];
    const float* be2 = (const float*)d_in[12];
    const float* Wc1 = (const float*)d_in[13];
    const float* bc1 = (const float*)d_in[14];
    const float* Wc2 = (const float*)d_in[15];
    const float* bc2 = (const float*)d_in[16];
    const float* Wd1 = (const float*)d_in[17];
    const float* bd1 = (const float*)d_in[18];
    const float* Wd2 = (const float*)d_in[19];
    const float* bd2 = (const float*)d_in[20];

    int n = in_sizes[0] / 3;
    int e = in_sizes[1] / 2;
    float* out = (float*)d_out;

    int nb256 = (n + 255) / 256;
    int eb256 = (e + 255) / 256;
    int mmb = (n + 7) / 8;
    double inv_n = 1.0 / (double)n;

    // CSR build
    k_init<<<nb256, 256>>>(n);
    k_prep_edges<<<eb256, 256>>>(ei, e, n);
    k_dinv_x4<<<nb256, 256>>>(x, n);
    k_degsum_block<<<nb256, 256>>>(n);
    k_scan_par<<<1, 512>>>(nb256, 0);
    k_rowstart<<<nb256, 256>>>(n);
    k_bucket<<<eb256, 256>>>(ei, e, n);

    // convs (matmul commuted after gather; BN folded)
    k_conv1<<<mmb, 256>>>(W1, b1, n);
    k_bnparams<<<1, dim3(32, 32)>>>(W2, g1, be1, inv_n);
    k_conv2<<<mmb, 256>>>(b2, n);
    k_bnparams<<<1, dim3(32, 32)>>>(W3, g2, be2, inv_n);
    k_conv3<<<mmb, 256>>>(b3, n);

    // heads
    k_softmax_acc<<<296, 256>>>(n);
    k_count<<<nb256, 256>>>(nt, n);
    k_scan_par<<<1, 512>>>(nb256, 1);
    k_cand<<<nb256, 256>>>(nt, Wc1, bc1, Wc2, bc2, out, n, out_size);
    k_dn<<<1, 32>>>(Wd1, bd1, Wd2, bd2, out, out_size);
}

// round 14
// speedup vs baseline: 1.2000x; 1.2000x over previous
#include <cuda_runtime.h>
#include <math.h>

#define NMAX 100000
#define EMAX 1600000
#define H 32
#define BN_EPS 1e-5f
#define NBANK 32
#define NBMAX ((NMAX + 255) / 256)

// ---------------- device scratch ----------------
__device__ int      g_csr[EMAX];
__device__ int      g_rowstart[NMAX];
__device__ int      g_cursor[NMAX];
__device__ int      g_deg[NMAX];
__device__ float    g_dinv[NMAX];
__device__ float    g_sdinv[NMAX];              // sum of dinv over nbrs + self
__device__ __align__(16) float4 g_x4[NMAX];     // (x*dinv, dinv)
__device__ __align__(16) float g_sA[NMAX * H];  // h'·dinv ping
__device__ __align__(16) float g_sB[NMAX * H];  // h'·dinv pong
__device__ __align__(16) float g_h[NMAX * H];   // final-layer features
__device__ float    g_r[NMAX];
__device__ double   g_sumb[NBANK][H], g_sumsqb[NBANK][H];  // banked BN stats
__device__ float    g_Wp[H * H];
__device__ float    g_kvec[H];
__device__ unsigned g_rmax_bits;
__device__ double   g_sumexp;
__device__ double   g_wsum[H];
__device__ int      g_blockcnt[NBMAX], g_blockoff[NBMAX], g_C;

__device__ __forceinline__ float warp_sum(float v) {
#pragma unroll
    for (int o = 16; o > 0; o >>= 1) v += __shfl_xor_sync(0xffffffffu, v, o);
    return v;
}

// ---------------- kernels ----------------
__global__ void k_init(int n) {
    int i = blockIdx.x * blockDim.x + threadIdx.x;
    if (i < n) { g_deg[i] = 0; g_cursor[i] = 0; }
    if (i < NBANK * H) { g_sumb[i >> 5][i & 31] = 0.0; g_sumsqb[i >> 5][i & 31] = 0.0; }
    if (i < H) g_wsum[i] = 0.0;
    if (i == 0) { g_rmax_bits = 0u; g_sumexp = 0.0; }
}

__global__ void k_prep_edges(const int* __restrict__ ei, int e, int n) {
    int t = blockIdx.x * blockDim.x + threadIdx.x;
    if (t >= e) return;
    int d = ei[e + t];
    if ((unsigned)d >= (unsigned)n) d = 0;
    atomicAdd(&g_deg[d], 1);
}

// fused: per-node dinv/x4 precompute + per-block deg scan
__global__ void k_dinv_degsum(const float* __restrict__ x, int n) {
    __shared__ int sh[256];
    int tid = threadIdx.x;
    int i = blockIdx.x * 256 + tid;
    int dv = (i < n) ? g_deg[i] : 0;
    if (i < n) {
        float di = rsqrtf((float)(dv + 1));
        g_dinv[i] = di;
        g_x4[i] = make_float4(x[(size_t)i * 3 + 0] * di,
                              x[(size_t)i * 3 + 1] * di,
                              x[(size_t)i * 3 + 2] * di, di);
    }
    sh[tid] = dv;
    __syncthreads();
#pragma unroll
    for (int off = 1; off < 256; off <<= 1) {
        int t = (tid >= off) ? sh[tid - off] : 0;
        __syncthreads();
        sh[tid] += t;
        __syncthreads();
    }
    if (tid == 255) g_blockcnt[blockIdx.x] = sh[255];
}

__global__ void k_scan_par(int nb, int setC) {
    __shared__ int sh[512];
    int tid = threadIdx.x;
    int v = (tid < nb) ? g_blockcnt[tid] : 0;
    sh[tid] = v;
    __syncthreads();
#pragma unroll
    for (int off = 1; off < 512; off <<= 1) {
        int t = (tid >= off) ? sh[tid - off] : 0;
        __syncthreads();
        sh[tid] += t;
        __syncthreads();
    }
    if (tid < nb) g_blockoff[tid] = sh[tid] - v;
    if (setC && tid == nb - 1) g_C = sh[tid];
}

__global__ void k_rowstart(int n) {
    __shared__ int sh[256];
    int tid = threadIdx.x;
    int i = blockIdx.x * 256 + tid;
    int v = (i < n) ? g_deg[i] : 0;
    sh[tid] = v;
    __syncthreads();
#pragma unroll
    for (int off = 1; off < 256; off <<= 1) {
        int t = (tid >= off) ? sh[tid - off] : 0;
        __syncthreads();
        sh[tid] += t;
        __syncthreads();
    }
    if (i < n) g_rowstart[i] = g_blockoff[blockIdx.x] + sh[tid] - v;
}

__global__ void k_bucket(const int* __restrict__ ei, int e, int n) {
    int t = blockIdx.x * blockDim.x + threadIdx.x;
    if (t >= e) return;
    int s = ei[t];
    int d = ei[e + t];
    if ((unsigned)s >= (unsigned)n) s = 0;
    if ((unsigned)d >= (unsigned)n) d = 0;
    int pos = g_rowstart[d] + atomicAdd(&g_cursor[d], 1);
    g_csr[pos] = s;
}

// conv1: rank-3 gather + W1 + bias/relu + banked stats; stores h1·dinv and sdinv
__global__ void k_conv1(const float* __restrict__ W, const float* __restrict__ bias,
                        int n) {
    __shared__ float Wsh[3 * H];
    __shared__ float sv[8][H], sq[8][H];
    int tid = threadIdx.x;
    for (int t = tid; t < 3 * H; t += 256) Wsh[t] = W[t];
    __syncthreads();
    int c = tid & 31, w = tid >> 5;
    int i = blockIdx.x * 8 + w;
    float v = 0.f;
    if (i < n) {
        int start = g_rowstart[i];
        int deg = g_deg[i];
        float ax = 0.f, ay = 0.f, az = 0.f, aw = 0.f;
        for (int k = c; k < deg; k += 32) {
            float4 t4 = g_x4[g_csr[start + k]];
            ax += t4.x; ay += t4.y; az += t4.z; aw += t4.w;
        }
        ax = warp_sum(ax); ay = warp_sum(ay); az = warp_sum(az); aw = warp_sum(aw);
        float4 self = g_x4[i];
        ax += self.x; ay += self.y; az += self.z; aw += self.w;
        if (c == 0) g_sdinv[i] = aw;
        float di = g_dinv[i];
        float z = ax * Wsh[0 * H + c] + ay * Wsh[1 * H + c] + az * Wsh[2 * H + c];
        v = fmaxf(z * di + bias[c], 0.f);
        g_sA[(size_t)i * H + c] = v * di;
    }
    sv[w][c] = v; sq[w][c] = v * v;
    __syncthreads();
    if (tid < H) {
        float s = 0.f, q = 0.f;
#pragma unroll
        for (int ww = 0; ww < 8; ww++) { s += sv[ww][tid]; q += sq[ww][tid]; }
        int b = blockIdx.x & (NBANK - 1);
        atomicAdd(&g_sumb[b][tid], (double)s);
        atomicAdd(&g_sumsqb[b][tid], (double)q);
    }
}

// BN params folded into next layer's weight (reads banked stats, zeroes them)
__global__ void k_bnparams(const float* __restrict__ W, const float* __restrict__ g,
                           const float* __restrict__ be, double inv_n) {
    __shared__ float sscale[H], sshift[H];
    int k = threadIdx.x, j = threadIdx.y;
    if (j == 0) {
        double s = 0.0, q = 0.0;
        for (int b = 0; b < NBANK; b++) { s += g_sumb[b][k]; q += g_sumsqb[b][k]; }
        double mu = s * inv_n;
        double var = q * inv_n - mu * mu;
        float scale = g[k] * rsqrtf((float)var + BN_EPS);
        sscale[k] = scale;
        sshift[k] = be[k] - (float)mu * scale;
    }
    __syncthreads();
    float wv = W[k * H + j];
    g_Wp[k * H + j] = sscale[k] * wv;
    float t = sshift[k] * wv;
#pragma unroll
    for (int o = 16; o > 0; o >>= 1) t += __shfl_xor_sync(0xffffffffu, t, o);
    if (k == 0) g_kvec[j] = t;
    g_sumb[j][k] = 0.0;
    g_sumsqb[j][k] = 0.0;
}

// conv2: unroll-8 gather + matmul after reduce + bias/relu + banked stats
__global__ void k_conv2(const float* __restrict__ bias, int n) {
    __shared__ float Wsh[H * H];
    __shared__ float kv[H];
    __shared__ float sv[8][H], sq[8][H];
    int tid = threadIdx.x;
    for (int t = tid; t < H * H; t += 256) Wsh[t] = g_Wp[t];
    if (tid < H) kv[tid] = g_kvec[tid];
    __syncthreads();
    int c = tid & 31, w = tid >> 5;
    int i = blockIdx.x * 8 + w;
    float v = 0.f;
    if (i < n) {
        float r = g_sA[(size_t)i * H + c];   // self
        int start = g_rowstart[i];
        int deg = g_deg[i];
        int k = 0;
        for (; k + 8 <= deg; k += 8) {
            int s0 = g_csr[start + k + 0], s1 = g_csr[start + k + 1];
            int s2 = g_csr[start + k + 2], s3 = g_csr[start + k + 3];
            int s4 = g_csr[start + k + 4], s5 = g_csr[start + k + 5];
            int s6 = g_csr[start + k + 6], s7 = g_csr[start + k + 7];
            float v0 = g_sA[(size_t)s0 * H + c], v1 = g_sA[(size_t)s1 * H + c];
            float v2 = g_sA[(size_t)s2 * H + c], v3 = g_sA[(size_t)s3 * H + c];
            float v4 = g_sA[(size_t)s4 * H + c], v5 = g_sA[(size_t)s5 * H + c];
            float v6 = g_sA[(size_t)s6 * H + c], v7 = g_sA[(size_t)s7 * H + c];
            r += ((v0 + v1) + (v2 + v3)) + ((v4 + v5) + (v6 + v7));
        }
        for (; k < deg; k++)
            r += g_sA[(size_t)g_csr[start + k] * H + c];
        float z = kv[c] * g_sdinv[i];
#pragma unroll
        for (int kk = 0; kk < H; kk++)
            z += __shfl_sync(0xffffffffu, r, kk) * Wsh[kk * H + c];
        float di = g_dinv[i];
        v = fmaxf(z * di + bias[c], 0.f);
        g_sB[(size_t)i * H + c] = v * di;
    }
    sv[w][c] = v; sq[w][c] = v * v;
    __syncthreads();
    if (tid < H) {
        float s = 0.f, q = 0.f;
#pragma unroll
        for (int ww = 0; ww < 8; ww++) { s += sv[ww][tid]; q += sq[ww][tid]; }
        int b = blockIdx.x & (NBANK - 1);
        atomicAdd(&g_sumb[b][tid], (double)s);
        atomicAdd(&g_sumsqb[b][tid], (double)q);
    }
}

// conv3: unroll-8 gather + matmul + bias/relu; store h; rowsum + block-level max
__global__ void k_conv3(const float* __restrict__ bias, int n) {
    __shared__ float Wsh[H * H];
    __shared__ float kv[H];
    __shared__ unsigned bmax;
    int tid = threadIdx.x;
    for (int t = tid; t < H * H; t += 256) Wsh[t] = g_Wp[t];
    if (tid < H) kv[tid] = g_kvec[tid];
    if (tid == 0) bmax = 0u;
    __syncthreads();
    int c = tid & 31, w = tid >> 5;
    int i = blockIdx.x * 8 + w;
    if (i < n) {
        float r = g_sB[(size_t)i * H + c];
        int start = g_rowstart[i];
        int deg = g_deg[i];
        int k = 0;
        for (; k + 8 <= deg; k += 8) {
            int s0 = g_csr[start + k + 0], s1 = g_csr[start + k + 1];
            int s2 = g_csr[start + k + 2], s3 = g_csr[start + k + 3];
            int s4 = g_csr[start + k + 4], s5 = g_csr[start + k + 5];
            int s6 = g_csr[start + k + 6], s7 = g_csr[start + k + 7];
            float v0 = g_sB[(size_t)s0 * H + c], v1 = g_sB[(size_t)s1 * H + c];
            float v2 = g_sB[(size_t)s2 * H + c], v3 = g_sB[(size_t)s3 * H + c];
            float v4 = g_sB[(size_t)s4 * H + c], v5 = g_sB[(size_t)s5 * H + c];
            float v6 = g_sB[(size_t)s6 * H + c], v7 = g_sB[(size_t)s7 * H + c];
            r += ((v0 + v1) + (v2 + v3)) + ((v4 + v5) + (v6 + v7));
        }
        for (; k < deg; k++)
            r += g_sB[(size_t)g_csr[start + k] * H + c];
        float z = kv[c] * g_sdinv[i];
#pragma unroll
        for (int kk = 0; kk < H; kk++)
            z += __shfl_sync(0xffffffffu, r, kk) * Wsh[kk * H + c];
        float v = fmaxf(z * g_dinv[i] + bias[c], 0.f);
        g_h[(size_t)i * H + c] = v;
        float rs = warp_sum(v);
        if (c == 0) {
            g_r[i] = rs;
            atomicMax(&bmax, __float_as_uint(rs));   // rs >= 0
        }
    }
    __syncthreads();
    if (tid == 0) atomicMax(&g_rmax_bits, bmax);
}

__global__ void k_softmax_acc(int n) {
    __shared__ double sw[H];
    __shared__ double se;
    int tid = threadIdx.x;
    if (tid < H) sw[tid] = 0.0;
    if (tid == 0) se = 0.0;
    __syncthreads();
    int lane = tid & 31;
    int gw = blockIdx.x * 8 + (tid >> 5);
    int nw = gridDim.x * 8;
    float rmax = __uint_as_float(g_rmax_bits);
    double acc = 0.0, eacc = 0.0;
    for (int i = gw; i < n; i += nw) {
        float ev = expf(g_r[i] - rmax);
        acc += (double)(ev * g_h[(size_t)i * H + lane]);
        if (lane == 0) eacc += (double)ev;
    }
    atomicAdd(&sw[lane], acc);
    if (lane == 0) atomicAdd(&se, eacc);
    __syncthreads();
    if (tid < H) atomicAdd(&g_wsum[tid], sw[tid]);
    if (tid == 0) atomicAdd(&g_sumexp, se);
}

__global__ void k_count(const int* __restrict__ nt, int n) {
    int i = blockIdx.x * 256 + threadIdx.x;
    int flag = (i < n && nt[i] == 0);
    int cnt = __syncthreads_count(flag);
    if (threadIdx.x == 0) g_blockcnt[blockIdx.x] = cnt;
}

__global__ void __launch_bounds__(256)
k_cand(const int* __restrict__ nt,
       const float* __restrict__ Wc1, const float* __restrict__ bc1,
       const float* __restrict__ Wc2, const float* __restrict__ bc2,
       float* __restrict__ out, int n, int out_size) {
    __shared__ float W1s[H * 16], b1s[16], W2s[16];
    __shared__ float b2s;
    __shared__ int warpsum[8], warpoff[8];
    int tid = threadIdx.x;
    for (int t = tid; t < H * 16; t += 256) W1s[t] = Wc1[t];
    if (tid < 16) { b1s[tid] = bc1[tid]; W2s[tid] = Wc2[tid]; }
    if (tid == 0) b2s = bc2[0];
    int i = blockIdx.x * 256 + tid;
    int flag = (i < n && nt[i] == 0);
    unsigned mask = __ballot_sync(0xffffffffu, flag);
    int lane = tid & 31, w = tid >> 5;
    if (lane == 0) warpsum[w] = __popc(mask);
    __syncthreads();
    if (tid == 0) {
        int run = 0;
#pragma unroll
        for (int ww = 0; ww < 8; ww++) { warpoff[ww] = run; run += warpsum[ww]; }
    }
    __syncthreads();
    if (!flag) return;
    int pos = g_blockoff[blockIdx.x] + warpoff[w] + __popc(mask & ((1u << lane) - 1));
    const float* hr = g_h + (size_t)i * H;
    float hreg[H];
#pragma unroll
    for (int k = 0; k < H; k++) hreg[k] = hr[k];
    float score = b2s;
#pragma unroll
    for (int j = 0; j < 16; j++) {
        float z = b1s[j];
#pragma unroll
        for (int k = 0; k < H; k++) z += hreg[k] * W1s[k * 16 + j];
        score += fmaxf(z, 0.f) * W2s[j];
    }
    int C = g_C;
    if (pos < out_size) out[pos] = score;
    int ip = C + 1 + pos;
    if (ip < out_size) out[ip] = (float)i;
}

__global__ void k_dn(const float* __restrict__ Wd1, const float* __restrict__ bd1,
                     const float* __restrict__ Wd2, const float* __restrict__ bd2,
                     float* __restrict__ out, int out_size) {
    int lane = threadIdx.x;
    double se = g_sumexp;
    float gv = (float)(g_wsum[lane] / se);
    float acc = (lane < 16) ? bd1[lane] : 0.f;
#pragma unroll
    for (int k = 0; k < H; k++) {
        float gk = __shfl_sync(0xffffffffu, gv, k);
        acc += gk * ((lane < 16) ? Wd1[k * 16 + lane] : 0.f);
    }
    float z = fmaxf(acc, 0.f);
    float t = (lane < 16) ? z * Wd2[lane] : 0.f;
    t = warp_sum(t);
    if (lane == 0) {
        int C = g_C;
        if (C < out_size) out[C] = t + bd2[0];
    }
}

// ---------------- host ----------------
extern "C" void kernel_launch(void* const* d_in, const int* in_sizes, int n_in,
                              void* d_out, int out_size) {
    const float* x   = (const float*)d_in[0];
    const int*   ei  = (const int*)d_in[1];
    const int*   nt  = (const int*)d_in[2];
    const float* W1  = (const float*)d_in[3];
    const float* b1  = (const float*)d_in[4];
    const float* W2  = (const float*)d_in[5];
    const float* b2  = (const float*)d_in[6];
    const float* W3  = (const float*)d_in[7];
    const float* b3  = (const float*)d_in[8];
    const float* g1  = (const float*)d_in[9];
    const float* be1 = (const float*)d_in[10];
    const float* g2  = (const float*)d_in[11];
    const float* be2 = (const float*)d_in[12];
    const float* Wc1 = (const float*)d_in[13];
    const float* bc1 = (const float*)d_in[14];
    const float* Wc2 = (const float*)d_in[15];
    const float* bc2 = (const float*)d_in[16];
    const float* Wd1 = (const float*)d_in[17];
    const float* bd1 = (const float*)d_in[18];
    const float* Wd2 = (const float*)d_in[19];
    const float* bd2 = (const float*)d_in[20];

    int n = in_sizes[0] / 3;
    int e = in_sizes[1] / 2;
    float* out = (float*)d_out;

    int nb256 = (n + 255) / 256;
    int eb256 = (e + 255) / 256;
    int mmb = (n + 7) / 8;
    double inv_n = 1.0 / (double)n;

    // CSR build
    k_init<<<nb256, 256>>>(n);
    k_prep_edges<<<eb256, 256>>>(ei, e, n);
    k_dinv_degsum<<<nb256, 256>>>(x, n);
    k_scan_par<<<1, 512>>>(nb256, 0);
    k_rowstart<<<nb256, 256>>>(n);
    k_bucket<<<eb256, 256>>>(ei, e, n);

    // convs (matmul commuted after gather; BN folded)
    k_conv1<<<mmb, 256>>>(W1, b1, n);
    k_bnparams<<<1, dim3(32, 32)>>>(W2, g1, be1, inv_n);
    k_conv2<<<mmb, 256>>>(b2, n);
    k_bnparams<<<1, dim3(32, 32)>>>(W3, g2, be2, inv_n);
    k_conv3<<<mmb, 256>>>(b3, n);

    // heads
    k_softmax_acc<<<296, 256>>>(n);
    k_count<<<nb256, 256>>>(nt, n);
    k_scan_par<<<1, 512>>>(nb256, 1);
    k_cand<<<nb256, 256>>>(nt, Wc1, bc1, Wc2, bc2, out, n, out_size);
    k_dn<<<1, 32>>>(Wd1, bd1, Wd2, bd2, out, out_size);
}